// round 1
// baseline (speedup 1.0000x reference)
#include <cuda_runtime.h>
#include <math.h>

#define D_MODEL 1024
#define NHEAD   16
#define HDIM    64
#define BATCH   2
#define SEQ     2048
#define MROWS   (BATCH*SEQ)   // 4096

// ---- scratch (allocation-free rule: device globals) ----
__device__ float g_qh[BATCH*NHEAD*SEQ*HDIM];  // [b,h,s,d]
__device__ float g_kh[BATCH*NHEAD*SEQ*HDIM];
__device__ float g_vh[BATCH*NHEAD*SEQ*HDIM];
__device__ float g_ao[MROWS*D_MODEL];         // attention output, [b,s,m]

// ============================================================
// GEMM: Y[i,n] = sum_m X[i,m] * W[n,m] + bias[n]
// X: [4096,1024] row-major, W: [1024,1024] row-major (both K-major -> NT gemm)
// dst_mode: 0/1/2 -> write g_qh/g_kh/g_vh in [b,h,s,d] layout
//           3     -> write Yext plain [i,n]
// x_sel: 0 -> use Xin param, 1 -> use g_ao
// ============================================================
__global__ __launch_bounds__(256)
void gemm_kernel(const float* __restrict__ Xin, int x_sel,
                 const float* __restrict__ Wm, const float* __restrict__ bias,
                 float* __restrict__ Yext, int dst_mode)
{
    __shared__ float As[64*33];
    __shared__ float Ws[64*33];
    const float* X = x_sel ? g_ao : Xin;

    const int tid = threadIdx.x;
    const int tx = tid & 15;      // 0..15 (N direction)
    const int ty = tid >> 4;      // 0..15 (M direction)
    const int n0 = blockIdx.x * 64;
    const int i0 = blockIdx.y * 64;

    float acc[4][4];
    #pragma unroll
    for (int ii = 0; ii < 4; ii++)
        #pragma unroll
        for (int jj = 0; jj < 4; jj++) acc[ii][jj] = 0.f;

    for (int kt = 0; kt < D_MODEL / 32; kt++) {
        const int k0 = kt * 32;
        #pragma unroll
        for (int r = 0; r < 8; r++) {
            int e = tid + 256 * r;
            int row = e >> 5, kk = e & 31;
            As[row * 33 + kk] = X[(size_t)(i0 + row) * D_MODEL + k0 + kk];
            Ws[row * 33 + kk] = Wm[(size_t)(n0 + row) * D_MODEL + k0 + kk];
        }
        __syncthreads();
        #pragma unroll
        for (int kk = 0; kk < 32; kk++) {
            float a[4], w[4];
            #pragma unroll
            for (int ii = 0; ii < 4; ii++) a[ii] = As[(4 * ty + ii) * 33 + kk];
            #pragma unroll
            for (int jj = 0; jj < 4; jj++) w[jj] = Ws[(4 * tx + jj) * 33 + kk];
            #pragma unroll
            for (int ii = 0; ii < 4; ii++)
                #pragma unroll
                for (int jj = 0; jj < 4; jj++)
                    acc[ii][jj] = fmaf(a[ii], w[jj], acc[ii][jj]);
        }
        __syncthreads();
    }

    if (dst_mode == 3) {
        #pragma unroll
        for (int ii = 0; ii < 4; ii++) {
            int i = i0 + 4 * ty + ii;
            #pragma unroll
            for (int jj = 0; jj < 4; jj++) {
                int n = n0 + 4 * tx + jj;
                Yext[(size_t)i * D_MODEL + n] = acc[ii][jj] + bias[n];
            }
        }
    } else {
        float* Y = (dst_mode == 0) ? g_qh : (dst_mode == 1) ? g_kh : g_vh;
        int h = n0 >> 6;   // N tile width 64 == head dim, so one head per tile
        #pragma unroll
        for (int ii = 0; ii < 4; ii++) {
            int i = i0 + 4 * ty + ii;
            int b = i >> 11;            // /2048
            int s = i & 2047;
            size_t base = ((size_t)(b * NHEAD + h) * SEQ + s) * HDIM;
            #pragma unroll
            for (int jj = 0; jj < 4; jj++) {
                int d = 4 * tx + jj;
                Y[base + d] = acc[ii][jj] + bias[n0 + d];
            }
        }
    }
}

// ============================================================
// Flash attention: one block per (bh, 64-row Q tile).
// Online softmax over 32 KV tiles of 64 keys. scale = 1/sqrt(1024).
// Thread grid 16x16, 4x4 register tiles. Lane = (ty&1)*16 + tx, so
// shuffle-xor {8,4,2,1} reduces over the 16 tx lanes (row direction).
// ============================================================
__global__ __launch_bounds__(256)
void flash_kernel()
{
    extern __shared__ float sm[];
    float* Qs = sm;                 // [64][65]
    float* Ks = sm + 64 * 65;       // [64][65], reused to stage P
    float* Vs = sm + 2 * 64 * 65;   // [64][65]

    const int tid = threadIdx.x;
    const int tx = tid & 15;
    const int ty = tid >> 4;
    const int qt = blockIdx.x;      // 0..31
    const int bh = blockIdx.y;      // 0..31

    const float* Q = g_qh + (size_t)bh * SEQ * HDIM;
    const float* K = g_kh + (size_t)bh * SEQ * HDIM;
    const float* V = g_vh + (size_t)bh * SEQ * HDIM;
    const int i0 = qt * 64;

    // load Q tile (coalesced, conflict-free stores with pad 65)
    #pragma unroll
    for (int r = 0; r < 16; r++) {
        int e = tid + 256 * r;
        int i = e >> 6, d = e & 63;
        Qs[i * 65 + d] = Q[(size_t)(i0 + i) * HDIM + d];
    }

    float m[4], l[4], O[4][4];
    #pragma unroll
    for (int ii = 0; ii < 4; ii++) {
        m[ii] = -1e30f; l[ii] = 0.f;
        #pragma unroll
        for (int jj = 0; jj < 4; jj++) O[ii][jj] = 0.f;
    }
    const float scale = 0.03125f;   // 1/sqrt(1024)

    for (int kt = 0; kt < SEQ / 64; kt++) {
        __syncthreads();            // prior PV reads done
        const int j0 = kt * 64;
        #pragma unroll
        for (int r = 0; r < 16; r++) {
            int e = tid + 256 * r;
            int j = e >> 6, d = e & 63;
            Ks[j * 65 + d] = K[(size_t)(j0 + j) * HDIM + d];
            Vs[j * 65 + d] = V[(size_t)(j0 + j) * HDIM + d];
        }
        __syncthreads();

        // S = Q K^T  (64x64 tile in 4x4 regs)
        float s[4][4];
        #pragma unroll
        for (int ii = 0; ii < 4; ii++)
            #pragma unroll
            for (int jj = 0; jj < 4; jj++) s[ii][jj] = 0.f;
        #pragma unroll 4
        for (int d = 0; d < 64; d++) {
            float qv[4], kv[4];
            #pragma unroll
            for (int ii = 0; ii < 4; ii++) qv[ii] = Qs[(4 * ty + ii) * 65 + d];
            #pragma unroll
            for (int jj = 0; jj < 4; jj++) kv[jj] = Ks[(4 * tx + jj) * 65 + d];
            #pragma unroll
            for (int ii = 0; ii < 4; ii++)
                #pragma unroll
                for (int jj = 0; jj < 4; jj++)
                    s[ii][jj] = fmaf(qv[ii], kv[jj], s[ii][jj]);
        }

        // online softmax (row reductions across the 16 tx lanes)
        float p[4][4];
        #pragma unroll
        for (int ii = 0; ii < 4; ii++) {
            float rm = -1e30f;
            #pragma unroll
            for (int jj = 0; jj < 4; jj++) {
                s[ii][jj] *= scale;
                rm = fmaxf(rm, s[ii][jj]);
            }
            #pragma unroll
            for (int off = 8; off >= 1; off >>= 1)
                rm = fmaxf(rm, __shfl_xor_sync(0xffffffffu, rm, off));
            float mn = fmaxf(m[ii], rm);
            float alpha = __expf(m[ii] - mn);
            float rs = 0.f;
            #pragma unroll
            for (int jj = 0; jj < 4; jj++) {
                p[ii][jj] = __expf(s[ii][jj] - mn);
                rs += p[ii][jj];
            }
            #pragma unroll
            for (int off = 8; off >= 1; off >>= 1)
                rs += __shfl_xor_sync(0xffffffffu, rs, off);
            l[ii] = l[ii] * alpha + rs;
            m[ii] = mn;
            #pragma unroll
            for (int jj = 0; jj < 4; jj++) O[ii][jj] *= alpha;
        }

        __syncthreads();            // all warps done reading Ks
        #pragma unroll
        for (int ii = 0; ii < 4; ii++)
            #pragma unroll
            for (int jj = 0; jj < 4; jj++)
                Ks[(4 * ty + ii) * 65 + (4 * tx + jj)] = p[ii][jj];
        __syncthreads();

        // O += P V
        #pragma unroll 4
        for (int j = 0; j < 64; j++) {
            float pv[4], vv[4];
            #pragma unroll
            for (int ii = 0; ii < 4; ii++) pv[ii] = Ks[(4 * ty + ii) * 65 + j];
            #pragma unroll
            for (int jj = 0; jj < 4; jj++) vv[jj] = Vs[j * 65 + (4 * tx + jj)];
            #pragma unroll
            for (int ii = 0; ii < 4; ii++)
                #pragma unroll
                for (int jj = 0; jj < 4; jj++)
                    O[ii][jj] = fmaf(pv[ii], vv[jj], O[ii][jj]);
        }
    }

    // epilogue: normalize and write to [b,s,m] layout
    const int b = bh >> 4, h = bh & 15;
    #pragma unroll
    for (int ii = 0; ii < 4; ii++) {
        float inv = 1.f / l[ii];
        int srow = i0 + 4 * ty + ii;
        size_t base = ((size_t)b * SEQ + srow) * D_MODEL + h * HDIM;
        #pragma unroll
        for (int jj = 0; jj < 4; jj++)
            g_ao[base + 4 * tx + jj] = O[ii][jj] * inv;
    }
}

// ============================================================
extern "C" void kernel_launch(void* const* d_in, const int* in_sizes, int n_in,
                              void* d_out, int out_size)
{
    const float* q  = (const float*)d_in[0];
    const float* k  = (const float*)d_in[1];
    const float* v  = (const float*)d_in[2];
    const float* Wq = (const float*)d_in[3];
    const float* bq = (const float*)d_in[4];
    const float* Wk = (const float*)d_in[5];
    const float* bk = (const float*)d_in[6];
    const float* Wv = (const float*)d_in[7];
    const float* bv = (const float*)d_in[8];
    const float* Wo = (const float*)d_in[9];
    const float* bo = (const float*)d_in[10];
    float* out = (float*)d_out;

    const int FLASH_SMEM = 3 * 64 * 65 * sizeof(float);  // 49920 B
    cudaFuncSetAttribute(flash_kernel,
                         cudaFuncAttributeMaxDynamicSharedMemorySize, FLASH_SMEM);

    dim3 blk(256);
    dim3 gp(D_MODEL / 64, MROWS / 64);   // (16, 64)

    gemm_kernel<<<gp, blk>>>(q, 0, Wq, bq, nullptr, 0);
    gemm_kernel<<<gp, blk>>>(k, 0, Wk, bk, nullptr, 1);
    gemm_kernel<<<gp, blk>>>(v, 0, Wv, bv, nullptr, 2);

    dim3 gf(SEQ / 64, BATCH * NHEAD);    // (32, 32)
    flash_kernel<<<gf, blk, FLASH_SMEM>>>();

    gemm_kernel<<<gp, blk>>>(nullptr, 1, Wo, bo, out, 3);
}